// round 6
// baseline (speedup 1.0000x reference)
#include <cuda_runtime.h>
#include <cuda_fp16.h>
#include <math.h>

// KDLayerNorm: per-row kernel-density CDF -> Gaussian PPF normalization.
// 2*cdf_i - 1 = (1/D) * sum_j erf((x_i-x_j)/(bw*sqrt2))
// erf(t) ~= tanh(t * q(min(t^2,12.25))), q quadratic; f32x2 packed + MUFU tanh.
// Antisymmetric exchange with TWO ROWS PER THREAD (t, t+128): one packed erf
// serves both rows at offset d; exchange values travel as one f16x2 word.

#define D 256
#define H 128              // threads per block
#define CW 16              // offsets per exchange chunk
#define NCH 8              // chunks cover d = 0..127 (d=0 contributes zeros)

typedef unsigned long long u64;

__device__ __forceinline__ float tanh_fast(float x) {
    float y; asm("tanh.approx.f32 %0, %1;" : "=f"(y) : "f"(x)); return y;
}
__device__ __forceinline__ u64 pack2(float lo, float hi) {
    u64 r; asm("mov.b64 %0, {%1, %2};" : "=l"(r) : "f"(lo), "f"(hi)); return r;
}
__device__ __forceinline__ void unpack2(u64 v, float& lo, float& hi) {
    asm("mov.b64 {%0, %1}, %2;" : "=f"(lo), "=f"(hi) : "l"(v));
}
__device__ __forceinline__ u64 add2(u64 a, u64 b) {
    u64 r; asm("add.rn.f32x2 %0, %1, %2;" : "=l"(r) : "l"(a), "l"(b)); return r;
}
__device__ __forceinline__ u64 mul2(u64 a, u64 b) {
    u64 r; asm("mul.rn.f32x2 %0, %1, %2;" : "=l"(r) : "l"(a), "l"(b)); return r;
}
__device__ __forceinline__ u64 fma2(u64 a, u64 b, u64 c) {
    u64 r; asm("fma.rn.f32x2 %0, %1, %2, %3;" : "=l"(r) : "l"(a), "l"(b), "l"(c)); return r;
}

// atanh(erf(x))/x quadratic-in-x^2 fit (interp at s=0, 2.25, 9; s clamped at 12.25)
#define QC0 1.1283792f
#define QC1 0.104728f
#define QC2 (-0.00208245f)
#define SMAX 12.25f

__global__ __launch_bounds__(H, 8)
void kdln_kernel(const float* __restrict__ x,
                 const float* __restrict__ weight,
                 const float* __restrict__ bias,
                 float* __restrict__ out)
{
    __shared__ u64 sxw[D];                    // word i = {-xs_(i), -xs_((i+128)%256)}  (2KB)
    __shared__ unsigned int sfh[CW][H];       // exchange buffer: f16x2 {f_d(j), f_d(j+128)} (8KB)
    __shared__ float wsum[4], wsq[4];

    const int row = blockIdx.x;
    const int t   = threadIdx.x;

    const float v0 = x[row * D + t];
    const float v1 = x[row * D + t + H];

    // --- row mean / var (ddof=1) over 256 values, 2 per thread ---
    float s = v0 + v1, s2 = v0 * v0 + v1 * v1;
    #pragma unroll
    for (int o = 16; o > 0; o >>= 1) {
        s  += __shfl_xor_sync(0xFFFFFFFFu, s,  o);
        s2 += __shfl_xor_sync(0xFFFFFFFFu, s2, o);
    }
    if ((t & 31) == 0) { wsum[t >> 5] = s; wsq[t >> 5] = s2; }
    __syncthreads();

    float S = 0.f, S2 = 0.f;
    #pragma unroll
    for (int i = 0; i < 4; i++) { S += wsum[i]; S2 += wsq[i]; }

    const float mean = S * (1.0f / D);
    const float var  = (S2 - (float)D * mean * mean) * (1.0f / (D - 1));
    // 0.9 * 256^(-0.2) = 0.2968892799239037
    const float bw   = 0.2968892799239037f * sqrtf(var);
    const float inv  = 1.0f / (bw * 1.4142135623730951f);  // 1/(bw*sqrt2)

    const float m0 = v0 * inv;
    const float m1 = v1 * inv;
    sxw[t]     = pack2(-m0, -m1);   // word t:      {-xs_t,     -xs_(t+128)}
    sxw[t + H] = pack2(-m1, -m0);   // word t+128:  {-xs_(t+128), -xs_t}
    __syncthreads();

    const u64 my2 = pack2(m0, m1);
    const u64 C0  = pack2(QC0, QC0);
    const u64 C1  = pack2(QC1, QC1);
    const u64 C2  = pack2(QC2, QC2);

    u64 accP0 = 0ull, accP1 = 0ull;   // direct terms   (rows t / t+128 in lo/hi)
    u64 accM0 = 0ull, accM1 = 0ull;   // exchanged terms

    for (int c = 0; c < NCH; c++) {
        const int dbase = c * CW;

        // --- compute phase: packed erf for both rows at offsets d = dbase..dbase+15 ---
        #pragma unroll
        for (int u = 0; u < CW; u++) {
            const int d = dbase + u;
            const u64 y2 = sxw[t + d];          // {-xs_(t+d), -xs_((t+d+128)%256)}
            const u64 tt = add2(my2, y2);
            const u64 sq = mul2(tt, tt);
            float sl, sh; unpack2(sq, sl, sh);
            sl = fminf(sl, SMAX);
            sh = fminf(sh, SMAX);
            const u64 sc = pack2(sl, sh);
            u64 q = fma2(sc, C2, C1);
            q = fma2(q, sc, C0);
            const u64 p = mul2(q, tt);
            float pl, ph; unpack2(p, pl, ph);
            const float fl = tanh_fast(pl);
            const float fh = tanh_fast(ph);
            const __half2 hh = __floats2half2_rn(fl, fh);
            sfh[u][t] = *(const unsigned int*)&hh;
            const u64 fp = pack2(fl, fh);
            if (u & 1) accP1 = add2(accP1, fp);
            else       accP0 = add2(accP0, fp);
        }
        __syncthreads();

        // --- exchange phase: row r picks up -f_d((r-d) mod 256) ---
        #pragma unroll
        for (int u = 0; u < CW; u++) {
            const int d = dbase + u;
            unsigned int g = sfh[u][(t - d) & (H - 1)];
            if (t < d) g = __byte_perm(g, 0, 0x1032);   // swap f16 halves on wrap
            const __half2 gh = *(const __half2*)&g;
            const float2 gf = __half22float2(gh);
            const u64 gp = pack2(gf.x, gf.y);
            if (u & 1) accM1 = add2(accM1, gp);
            else       accM0 = add2(accM0, gp);
        }
        __syncthreads();   // sfh reused next chunk
    }

    // --- d = 128: self-dual within the thread (rows t and t+128 are partners) ---
    const float t128 = m0 - m1;
    const float s128 = fminf(t128 * t128, SMAX);
    const float p128 = fmaf(fmaf(QC2, s128, QC1), s128, QC0) * t128;
    const float e128 = tanh_fast(p128);

    float Pl, Ph, Ml, Mh;
    unpack2(add2(accP0, accP1), Pl, Ph);
    unpack2(add2(accM0, accM1), Ml, Mh);
    const float acc_lo = Pl - Ml + e128;
    const float acc_hi = Ph - Mh - e128;

    // 2*cdf - 1 = acc / D
    const float n0 = erfinvf(acc_lo * (1.0f / D)) * 1.4142135623730951f;
    const float n1 = erfinvf(acc_hi * (1.0f / D)) * 1.4142135623730951f;
    out[row * D + t]     = n0 * weight[t]     + bias[t];
    out[row * D + t + H] = n1 * weight[t + H] + bias[t + H];
}

extern "C" void kernel_launch(void* const* d_in, const int* in_sizes, int n_in,
                              void* d_out, int out_size)
{
    const float* x = (const float*)d_in[0];
    const float* w = (const float*)d_in[1];
    const float* b = (const float*)d_in[2];
    float* out = (float*)d_out;

    const int n_rows = in_sizes[0] / D;   // 4096
    kdln_kernel<<<n_rows, H>>>(x, w, b, out);
}